// round 7
// baseline (speedup 1.0000x reference)
#include <cuda_runtime.h>
#include <cstdint>

// EdgeDecoder: out[g] = relu(concat(zA[g], zB[g]) @ w1 + b1) @ w2 + b2
// for 3 edge types concatenated [ptnp | nptp | nptnp], E edges each.
//
// sm_103 (no 'a' features!) tensor path: mma.sync m16n8k8 tf32.
// Persistent kernel, 148 CTAs x 256 threads. Each warp: M=32 edges tile,
// full fp32 accumulator (128 regs), k outer / n inner. A gathered directly
// from global (depth-2 prefetch), B = w1 resident in smem as per-fragment
// uint2 pairs (conflict-free LDS.64, pipelined depth 2). Epilogue fuses
// bias+relu+dot(w2) per fragment with quad shuffle reduction.

#define E_CNT    500000
#define TOTAL    1500000
#define NTILES   5860            // ceil(TOTAL / 256)
#define NCTAS    148
#define NTHREADS 256

#define SM_B_BYTES (32 * 16 * 32 * 8)          // 131072: B frags [kc][nt][lane] uint2
#define SM_TOTAL   (SM_B_BYTES + 64 * 8 + 64 * 8)

static __device__ __forceinline__ uint32_t f2tf32(float x) {
    uint32_t r;
    asm("cvt.rna.tf32.f32 %0, %1;" : "=r"(r) : "f"(x));
    return r;
}

// D(16x8) += A(16x8,row) * B(8x8,col), tf32 in, f32 accumulate (in place).
#define MMA(d, A0, A1, A2, A3, B)                                        \
    asm volatile(                                                        \
        "mma.sync.aligned.m16n8k8.row.col.f32.tf32.tf32.f32 "            \
        "{%0,%1,%2,%3}, {%4,%5,%6,%7}, {%8,%9}, {%0,%1,%2,%3};"          \
        : "+f"((d)[0]), "+f"((d)[1]), "+f"((d)[2]), "+f"((d)[3])         \
        : "r"(A0), "r"(A1), "r"(A2), "r"(A3), "r"((B).x), "r"((B).y))

// Load 8 raw A floats for one k-chunk (kk in 0..15 within the half selected
// by pointer array P): rows qr+{0,8,16,24}, cols kk*8 + qc and + qc+4.
#define LOADA(dst, P, kk)                                                \
    do {                                                                 \
        _Pragma("unroll")                                                \
        for (int ri_ = 0; ri_ < 4; ri_++) {                              \
            const float* q_ = (P)[ri_] + (kk) * 8 + qc;                  \
            (dst)[ri_ * 2]     = __ldg(q_);                              \
            (dst)[ri_ * 2 + 1] = __ldg(q_ + 4);                          \
        }                                                                \
    } while (0)

#define BS(kc, nt) Bsm[((kc) * 16 + (nt)) * 32 + lane]

__global__ void __launch_bounds__(NTHREADS, 1)
edgedecoder_kernel(const float* __restrict__ zp, const float* __restrict__ zo,
                   const int* __restrict__ e0, const int* __restrict__ e1,
                   const int* __restrict__ e2,
                   const float* __restrict__ w1, const float* __restrict__ b1,
                   const float* __restrict__ w2, const float* __restrict__ b2,
                   float* __restrict__ out) {
    extern __shared__ char smem[];
    uint2* Bst = (uint2*)smem;
    const uint2* Bsm = (const uint2*)smem;
    float2* b1p = (float2*)(smem + SM_B_BYTES);
    float2* w2p = b1p + 64;

    const int tid  = threadIdx.x;
    const int warp = tid >> 5;
    const int lane = tid & 31;
    const int qr   = lane >> 2;   // quad row 0..7
    const int qc   = lane & 3;    // quad col 0..3

    // ---- stage B = w1 (256x128 row-major) as per-fragment tf32 pairs ----
    // frag element for (kc, nt, lane): b.x = w1[kc*8 + lane%4][nt*8 + lane/4]
    //                                  b.y = same with k + 4
    for (int i = tid; i < 32 * 16 * 32; i += NTHREADS) {
        int li = i & 31, nt = (i >> 5) & 15, kc = i >> 9;
        int k0 = kc * 8 + (li & 3);
        int n  = nt * 8 + (li >> 2);
        uint2 v;
        v.x = f2tf32(w1[k0 * 128 + n]);
        v.y = f2tf32(w1[(k0 + 4) * 128 + n]);
        Bst[i] = v;
    }
    if (tid < 64) {
        b1p[tid] = ((const float2*)b1)[tid];
        w2p[tid] = ((const float2*)w2)[tid];
    }
    __syncthreads();

    const float b2v = __ldg(b2);

    for (int tile = blockIdx.x; tile < NTILES; tile += NCTAS) {
        const int base = tile * 256 + warp * 32;

        // ---- per-lane gather pointers for its 4 rows (qr + ri*8) ----
        const float* p0[4];   // first 128 features (endpoint 0)
        const float* p1[4];   // second 128 features (endpoint 1)
#pragma unroll
        for (int ri = 0; ri < 4; ri++) {
            int g  = base + qr + ri * 8;
            int gg = (g < TOTAL) ? g : (TOTAL - 1);
            const int* ei;
            const float *t0, *t1;
            int e;
            if (gg < E_CNT)          { ei = e0; t0 = zp; t1 = zo; e = gg; }
            else if (gg < 2 * E_CNT) { ei = e1; t0 = zo; t1 = zp; e = gg - E_CNT; }
            else                     { ei = e2; t0 = zo; t1 = zo; e = gg - 2 * E_CNT; }
            p0[ri] = t0 + (size_t)__ldg(ei + e) * 128;
            p1[ri] = t1 + (size_t)__ldg(ei + E_CNT + e) * 128;
        }

        // ---- accumulators: [m-frag][n-tile][4] = 32x128 fp32 ----
        float acc[2][16][4];
#pragma unroll
        for (int mf = 0; mf < 2; mf++)
#pragma unroll
            for (int nt = 0; nt < 16; nt++)
#pragma unroll
                for (int j = 0; j < 4; j++) acc[mf][nt][j] = 0.f;

        float ar0[8], ar1[8];
        LOADA(ar0, p0, 0);
        LOADA(ar1, p0, 1);

        // ---- K half 0: kc 0..15 (endpoint-0 features) ----
#pragma unroll
        for (int kc = 0; kc < 16; kc++) {
            float* cur = (kc & 1) ? ar1 : ar0;
            uint32_t at[8];
#pragma unroll
            for (int j = 0; j < 8; j++) at[j] = f2tf32(cur[j]);
            if (kc < 14) { LOADA(cur, p0, kc + 2); }
            else         { LOADA(cur, p1, kc - 14); }

            uint2 bA = BS(kc, 0), bB = BS(kc, 1), bC;
#pragma unroll
            for (int nt = 0; nt < 16; nt++) {
                if (nt < 14) bC = BS(kc, nt + 2);
                MMA(acc[0][nt], at[0], at[2], at[1], at[3], bA);
                MMA(acc[1][nt], at[4], at[6], at[5], at[7], bA);
                bA = bB; bB = bC;
            }
        }

        // ---- K half 1: kc 16..31 (endpoint-1 features) ----
#pragma unroll
        for (int kc = 0; kc < 16; kc++) {
            float* cur = (kc & 1) ? ar1 : ar0;
            uint32_t at[8];
#pragma unroll
            for (int j = 0; j < 8; j++) at[j] = f2tf32(cur[j]);
            if (kc < 14) { LOADA(cur, p1, kc + 2); }

            uint2 bA = BS(kc + 16, 0), bB = BS(kc + 16, 1), bC;
#pragma unroll
            for (int nt = 0; nt < 16; nt++) {
                if (nt < 14) bC = BS(kc + 16, nt + 2);
                MMA(acc[0][nt], at[0], at[2], at[1], at[3], bA);
                MMA(acc[1][nt], at[4], at[6], at[5], at[7], bA);
                bA = bB; bB = bC;
            }
        }

        // ---- epilogue: s[ri] = sum_n relu(h + b1) * w2, rows qr + ri*8 ----
        float s[4] = {0.f, 0.f, 0.f, 0.f};
#pragma unroll
        for (int nt = 0; nt < 16; nt++) {
            float2 bb = b1p[nt * 4 + qc];   // b1[n], b1[n+1], n = nt*8 + qc*2
            float2 ww = w2p[nt * 4 + qc];
#pragma unroll
            for (int mf = 0; mf < 2; mf++) {
                float v0 = fmaxf(acc[mf][nt][0] + bb.x, 0.f);
                float v1 = fmaxf(acc[mf][nt][1] + bb.y, 0.f);
                float v2 = fmaxf(acc[mf][nt][2] + bb.x, 0.f);
                float v3 = fmaxf(acc[mf][nt][3] + bb.y, 0.f);
                s[mf * 2]     = fmaf(v0, ww.x, fmaf(v1, ww.y, s[mf * 2]));
                s[mf * 2 + 1] = fmaf(v2, ww.x, fmaf(v3, ww.y, s[mf * 2 + 1]));
            }
        }
        // reduce across the 4 lanes of the quad (qc = 0..3 are lanes qr*4+qc)
#pragma unroll
        for (int ri = 0; ri < 4; ri++) {
            s[ri] += __shfl_xor_sync(0xffffffffu, s[ri], 1);
            s[ri] += __shfl_xor_sync(0xffffffffu, s[ri], 2);
        }
        if (qc == 0) {
#pragma unroll
            for (int ri = 0; ri < 4; ri++) {
                int g = base + qr + ri * 8;
                if (g < TOTAL) out[g] = s[ri] + b2v;
            }
        }
    }
}

extern "C" void kernel_launch(void* const* d_in, const int* in_sizes, int n_in,
                              void* d_out, int out_size) {
    (void)in_sizes; (void)n_in; (void)out_size;
    const float* zp    = (const float*)d_in[0];
    const float* zo    = (const float*)d_in[1];
    const int*   ptnp  = (const int*)d_in[2];
    const int*   nptp  = (const int*)d_in[3];
    const int*   nptnp = (const int*)d_in[4];
    const float* w1    = (const float*)d_in[5];
    const float* b1    = (const float*)d_in[6];
    const float* w2    = (const float*)d_in[7];
    const float* b2    = (const float*)d_in[8];
    float* out = (float*)d_out;

    cudaFuncSetAttribute(edgedecoder_kernel,
                         cudaFuncAttributeMaxDynamicSharedMemorySize, SM_TOTAL);
    edgedecoder_kernel<<<NCTAS, NTHREADS, SM_TOTAL>>>(
        zp, zo, ptnp, nptp, nptnp, w1, b1, w2, b2, out);
}

// round 10
// speedup vs baseline: 1.8812x; 1.8812x over previous
#include <cuda_runtime.h>
#include <cstdint>

// EdgeDecoder: out[g] = relu(concat(zA[g], zB[g]) @ w1 + b1) @ w2 + b2
// for 3 edge types concatenated [ptnp | nptp | nptnp], E edges each.
//
// sm_103 (no 'a' features) tensor path: mma.sync m16n8k8 tf32.
// Persistent, 148 CTAs x 256 threads, warp owns M=32 edges x N=128 x K=256.
// Gather now goes through cp.async.cg (coalesced 128B rows) into a
// double-buffered smem staging tile (8 stages of 32 rows x 32 cols),
// fragments fed by conflict-free LDS.32. B = w1 tf32 frags resident in smem.

#define E_CNT    500000
#define TOTAL    1500000
#define NTILES   5860            // ceil(TOTAL / 256)
#define NCTAS    148
#define NTHREADS 256

// ---- smem layout (bytes) ----
#define SM_B     0               // 131072: B frags [kc][nt][lane] uint2
#define SM_B1    131072          // 512: b1 as float2[64]
#define SM_W2    131584          // 512: w2 as float2[64]
#define SM_RPTR  132096          // 4096: per-warp 32 rows x {p0,p1} (16B)
#define SM_A     136192          // 73728: per-warp 2 x 4608B staging
#define SM_TOTAL 209920

#define ROW_STRIDE 144           // 36 floats per staged row (32 + pad)
#define STG_BYTES  4608          // 32 rows * 144B

static __device__ __forceinline__ uint32_t s2u(const void* p) {
    uint32_t a;
    asm("{ .reg .u64 t; cvta.to.shared.u64 t, %1; cvt.u32.u64 %0, t; }"
        : "=r"(a) : "l"(p));
    return a;
}
static __device__ __forceinline__ uint32_t f2tf32(float x) {
    uint32_t r;
    asm("cvt.rna.tf32.f32 %0, %1;" : "=r"(r) : "f"(x));
    return r;
}
static __device__ __forceinline__ void cp16(uint32_t dst, const void* src) {
    asm volatile("cp.async.cg.shared.global [%0], [%1], 16;"
                 :: "r"(dst), "l"(src) : "memory");
}
#define CP_COMMIT asm volatile("cp.async.commit_group;" ::: "memory")
#define CP_WAIT1  asm volatile("cp.async.wait_group 1;" ::: "memory")
#define CP_WAIT0  asm volatile("cp.async.wait_group 0;" ::: "memory")

// D(16x8) += A(16x8,row) * B(8x8,col), tf32 in, f32 accumulate (in place).
#define MMA(d, A0, A1, A2, A3, B)                                        \
    asm volatile(                                                        \
        "mma.sync.aligned.m16n8k8.row.col.f32.tf32.tf32.f32 "            \
        "{%0,%1,%2,%3}, {%4,%5,%6,%7}, {%8,%9}, {%0,%1,%2,%3};"          \
        : "+f"((d)[0]), "+f"((d)[1]), "+f"((d)[2]), "+f"((d)[3])         \
        : "r"(A0), "r"(A1), "r"(A2), "r"(A3), "r"((B).x), "r"((B).y))

#define BS(kc, nt) Bsm[((kc) * 16 + (nt)) * 32 + lane]

__global__ void __launch_bounds__(NTHREADS, 1)
edgedecoder_kernel(const float* __restrict__ zp, const float* __restrict__ zo,
                   const int* __restrict__ e0, const int* __restrict__ e1,
                   const int* __restrict__ e2,
                   const float* __restrict__ w1, const float* __restrict__ b1,
                   const float* __restrict__ w2, const float* __restrict__ b2,
                   float* __restrict__ out) {
    extern __shared__ char smem[];
    uint2* Bst = (uint2*)(smem + SM_B);
    const uint2* Bsm = (const uint2*)(smem + SM_B);
    float2* b1p = (float2*)(smem + SM_B1);
    float2* w2p = (float2*)(smem + SM_W2);

    const int tid  = threadIdx.x;
    const int warp = tid >> 5;
    const int lane = tid & 31;
    const int qr   = lane >> 2;   // quad row 0..7
    const int qc   = lane & 3;    // quad col 0..3

    const uint32_t sb     = s2u(smem);
    const uint32_t a_s    = sb + SM_A + warp * (2 * STG_BYTES);
    char*          a_c    = smem + SM_A + warp * (2 * STG_BYTES);
    char*          rptr_c = smem + SM_RPTR + warp * 512;

    // ---- stage B = w1 (256x128 row-major) as per-fragment tf32 pairs ----
    for (int i = tid; i < 32 * 16 * 32; i += NTHREADS) {
        int li = i & 31, nt = (i >> 5) & 15, kc = i >> 9;
        int k0 = kc * 8 + (li & 3);
        int n  = nt * 8 + (li >> 2);
        uint2 v;
        v.x = f2tf32(w1[k0 * 128 + n]);
        v.y = f2tf32(w1[(k0 + 4) * 128 + n]);
        Bst[i] = v;
    }
    if (tid < 64) {
        b1p[tid] = ((const float2*)b1)[tid];
        w2p[tid] = ((const float2*)w2)[tid];
    }
    __syncthreads();

    const float b2v = __ldg(b2);
    const int rr   = lane >> 3;   // staging row-in-group 0..3
    const int cseg = lane & 7;    // staging float4 segment 0..7

    for (int tile = blockIdx.x; tile < NTILES; tile += NCTAS) {
        const int base = tile * 256 + warp * 32;

        // ---- per-row gather pointers into smem (row = lane) ----
        {
            int g  = base + lane;
            int gg = (g < TOTAL) ? g : (TOTAL - 1);
            const int* ei;
            const float *t0, *t1;
            int e;
            if (gg < E_CNT)          { ei = e0; t0 = zp; t1 = zo; e = gg; }
            else if (gg < 2 * E_CNT) { ei = e1; t0 = zo; t1 = zp; e = gg - E_CNT; }
            else                     { ei = e2; t0 = zo; t1 = zo; e = gg - 2 * E_CNT; }
            ulonglong2 pp;
            pp.x = (unsigned long long)(t0 + (size_t)__ldg(ei + e) * 128);
            pp.y = (unsigned long long)(t1 + (size_t)__ldg(ei + E_CNT + e) * 128);
            *(ulonglong2*)(rptr_c + lane * 16) = pp;
        }
        __syncwarp();

        // ---- accumulators: 32 edges x 128 hidden ----
        float acc[2][16][4];
#pragma unroll
        for (int mf = 0; mf < 2; mf++)
#pragma unroll
            for (int nt = 0; nt < 16; nt++)
#pragma unroll
                for (int j = 0; j < 4; j++) acc[mf][nt][j] = 0.f;

        // ---- prologue: stage 0 ----
        {
            const int coloff = cseg * 4;
#pragma unroll
            for (int r = 0; r < 8; r++) {
                const int row = r * 4 + rr;
                const ulonglong2 pp = *(const ulonglong2*)(rptr_c + row * 16);
                cp16(a_s + row * ROW_STRIDE + cseg * 16,
                     (const float*)pp.x + coloff);
            }
            CP_COMMIT;
        }

        // ---- 8 stages of 32 K-columns each ----
#pragma unroll 2
        for (int s = 0; s < 8; s++) {
            const uint32_t abuf_next = a_s + (((s + 1) & 1) ? STG_BYTES : 0);
            if (s < 7) {
                const int sn = s + 1;
                const int coloff = (sn & 3) * 32 + cseg * 4;
#pragma unroll
                for (int r = 0; r < 8; r++) {
                    const int row = r * 4 + rr;
                    const ulonglong2 pp = *(const ulonglong2*)(rptr_c + row * 16);
                    const float* p = (sn >= 4) ? (const float*)pp.y
                                               : (const float*)pp.x;
                    cp16(abuf_next + row * ROW_STRIDE + cseg * 16, p + coloff);
                }
                CP_COMMIT;
                CP_WAIT1;
            } else {
                CP_WAIT0;
            }
            __syncwarp();

            const char* ab = a_c + ((s & 1) ? STG_BYTES : 0);
#pragma unroll
            for (int kc4 = 0; kc4 < 4; kc4++) {
                const int kcg = s * 4 + kc4;
                const char* abase = ab + (kc4 * 8 + qc) * 4 + qr * ROW_STRIDE;
                uint32_t at[8];
                at[0] = f2tf32(*(const float*)(abase));
                at[1] = f2tf32(*(const float*)(abase + 8 * ROW_STRIDE));
                at[2] = f2tf32(*(const float*)(abase + 16));
                at[3] = f2tf32(*(const float*)(abase + 8 * ROW_STRIDE + 16));
                at[4] = f2tf32(*(const float*)(abase + 16 * ROW_STRIDE));
                at[5] = f2tf32(*(const float*)(abase + 24 * ROW_STRIDE));
                at[6] = f2tf32(*(const float*)(abase + 16 * ROW_STRIDE + 16));
                at[7] = f2tf32(*(const float*)(abase + 24 * ROW_STRIDE + 16));

                uint2 bA = BS(kcg, 0), bB = BS(kcg, 1), bC;
#pragma unroll
                for (int nt = 0; nt < 16; nt++) {
                    if (nt < 14) bC = BS(kcg, nt + 2);
                    MMA(acc[0][nt], at[0], at[1], at[2], at[3], bA);
                    MMA(acc[1][nt], at[4], at[5], at[6], at[7], bA);
                    bA = bB; bB = bC;
                }
            }
            __syncwarp();
        }

        // ---- epilogue: s[ri] = sum_n relu(h + b1) * w2 ----
        float s4[4] = {0.f, 0.f, 0.f, 0.f};
#pragma unroll
        for (int nt = 0; nt < 16; nt++) {
            float2 bb = b1p[nt * 4 + qc];
            float2 ww = w2p[nt * 4 + qc];
#pragma unroll
            for (int mf = 0; mf < 2; mf++) {
                float v0 = fmaxf(acc[mf][nt][0] + bb.x, 0.f);
                float v1 = fmaxf(acc[mf][nt][1] + bb.y, 0.f);
                float v2 = fmaxf(acc[mf][nt][2] + bb.x, 0.f);
                float v3 = fmaxf(acc[mf][nt][3] + bb.y, 0.f);
                s4[mf * 2]     = fmaf(v0, ww.x, fmaf(v1, ww.y, s4[mf * 2]));
                s4[mf * 2 + 1] = fmaf(v2, ww.x, fmaf(v3, ww.y, s4[mf * 2 + 1]));
            }
        }
#pragma unroll
        for (int ri = 0; ri < 4; ri++) {
            s4[ri] += __shfl_xor_sync(0xffffffffu, s4[ri], 1);
            s4[ri] += __shfl_xor_sync(0xffffffffu, s4[ri], 2);
        }
        if (qc == 0) {
#pragma unroll
            for (int ri = 0; ri < 4; ri++) {
                int g = base + qr + ri * 8;
                if (g < TOTAL) out[g] = s4[ri] + b2v;
            }
        }
    }
}

extern "C" void kernel_launch(void* const* d_in, const int* in_sizes, int n_in,
                              void* d_out, int out_size) {
    (void)in_sizes; (void)n_in; (void)out_size;
    const float* zp    = (const float*)d_in[0];
    const float* zo    = (const float*)d_in[1];
    const int*   ptnp  = (const int*)d_in[2];
    const int*   nptp  = (const int*)d_in[3];
    const int*   nptnp = (const int*)d_in[4];
    const float* w1    = (const float*)d_in[5];
    const float* b1    = (const float*)d_in[6];
    const float* w2    = (const float*)d_in[7];
    const float* b2    = (const float*)d_in[8];
    float* out = (float*)d_out;

    cudaFuncSetAttribute(edgedecoder_kernel,
                         cudaFuncAttributeMaxDynamicSharedMemorySize, SM_TOTAL);
    edgedecoder_kernel<<<NCTAS, NTHREADS, SM_TOTAL>>>(
        zp, zo, ptnp, nptp, nptnp, w1, b1, w2, b2, out);
}

// round 12
// speedup vs baseline: 2.6606x; 1.4143x over previous
#include <cuda_runtime.h>
#include <cstdint>

// EdgeDecoder: out[g] = relu(concat(zA[g], zB[g]) @ w1 + b1) @ w2 + b2
// for 3 edge types concatenated [ptnp | nptp | nptnp], E edges each.
//
// sm_103 (no 'a' features) tensor path: mma.sync m16n8k16 FP16 (10-bit
// mantissa = tf32 precision, 2x K per instruction vs tf32 k8).
// Persistent, 148 CTAs x 256 threads, warp owns M=32 edges x N=128 x K=256.
// Gather via cp.async.cg into 3-deep per-warp fp32 staging (8 stages of
// 32 rows x 32 cols); A frags = LDS.64 + cvt.rn.f16x2; B = w1 as packed
// fp16x2 frag pairs resident in smem. Epilogue fuses bias+relu+dot(w2).

#define E_CNT    500000
#define TOTAL    1500000
#define NTILES   5860            // ceil(TOTAL / 256)
#define NCTAS    148
#define NTHREADS 256

// ---- smem layout (bytes) ----
#define SM_B     0               // 65536: B frags [kc(16)][nt(16)][lane] uint2
#define SM_B1    65536           // 512: b1 as float2[64]
#define SM_W2    66048           // 512: w2 as float2[64]
#define SM_RPTR  66560           // 4096: per-warp 32 rows x {p0,p1} (16B)
#define SM_A     70656           // 110592: per-warp 3 x 4608B staging
#define SM_TOTAL 181248

#define ROW_STRIDE 144           // 36 floats per staged row (32 + pad)
#define STG_BYTES  4608          // 32 rows * 144B

static __device__ __forceinline__ uint32_t s2u(const void* p) {
    uint32_t a;
    asm("{ .reg .u64 t; cvta.to.shared.u64 t, %1; cvt.u32.u64 %0, t; }"
        : "=r"(a) : "l"(p));
    return a;
}
// pack (lo, hi) fp32 -> fp16x2 register (round to nearest even)
static __device__ __forceinline__ uint32_t packh2(float lo, float hi) {
    uint32_t r;
    asm("cvt.rn.f16x2.f32 %0, %1, %2;" : "=r"(r) : "f"(hi), "f"(lo));
    return r;
}
static __device__ __forceinline__ void cp16(uint32_t dst, const void* src) {
    asm volatile("cp.async.cg.shared.global [%0], [%1], 16;"
                 :: "r"(dst), "l"(src) : "memory");
}
#define CP_COMMIT asm volatile("cp.async.commit_group;" ::: "memory")
#define CP_WAIT2  asm volatile("cp.async.wait_group 2;" ::: "memory")
#define CP_WAIT1  asm volatile("cp.async.wait_group 1;" ::: "memory")
#define CP_WAIT0  asm volatile("cp.async.wait_group 0;" ::: "memory")

// D(16x8) += A(16x16,row,f16) * B(16x8,col,f16), fp32 accumulate in place.
#define MMA(d, A0, A1, A2, A3, B)                                        \
    asm volatile(                                                        \
        "mma.sync.aligned.m16n8k16.row.col.f32.f16.f16.f32 "             \
        "{%0,%1,%2,%3}, {%4,%5,%6,%7}, {%8,%9}, {%0,%1,%2,%3};"          \
        : "+f"((d)[0]), "+f"((d)[1]), "+f"((d)[2]), "+f"((d)[3])         \
        : "r"(A0), "r"(A1), "r"(A2), "r"(A3), "r"((B).x), "r"((B).y))

#define BS(kc, nt) Bsm[((kc) * 16 + (nt)) * 32 + lane]

// issue cp.async for one 32-col stage sn (0..7) into buffer sn%3
#define ISSUE_STAGE(sn)                                                    \
    do {                                                                   \
        const int co_ = ((sn) & 3) * 32 + cseg * 4;                        \
        const uint32_t dst_ = a_s + ((sn) % 3) * STG_BYTES;                \
        _Pragma("unroll")                                                  \
        for (int r_ = 0; r_ < 8; r_++) {                                   \
            const int row_ = r_ * 4 + rr;                                  \
            const ulonglong2 pp_ =                                         \
                *(const ulonglong2*)(rptr_c + row_ * 16);                  \
            const float* p_ = ((sn) >= 4) ? (const float*)pp_.y            \
                                          : (const float*)pp_.x;           \
            cp16(dst_ + row_ * ROW_STRIDE + cseg * 16, p_ + co_);          \
        }                                                                  \
        CP_COMMIT;                                                         \
    } while (0)

__global__ void __launch_bounds__(NTHREADS, 1)
edgedecoder_kernel(const float* __restrict__ zp, const float* __restrict__ zo,
                   const int* __restrict__ e0, const int* __restrict__ e1,
                   const int* __restrict__ e2,
                   const float* __restrict__ w1, const float* __restrict__ b1,
                   const float* __restrict__ w2, const float* __restrict__ b2,
                   float* __restrict__ out) {
    extern __shared__ char smem[];
    uint2* Bst = (uint2*)(smem + SM_B);
    const uint2* Bsm = (const uint2*)(smem + SM_B);
    float2* b1p = (float2*)(smem + SM_B1);
    float2* w2p = (float2*)(smem + SM_W2);

    const int tid  = threadIdx.x;
    const int warp = tid >> 5;
    const int lane = tid & 31;
    const int qr   = lane >> 2;   // group id 0..7
    const int qc   = lane & 3;    // thread-in-group 0..3

    const uint32_t a_s    = s2u(smem) + SM_A + warp * (3 * STG_BYTES);
    char*          a_c    = smem + SM_A + warp * (3 * STG_BYTES);
    char*          rptr_c = smem + SM_RPTR + warp * 512;

    // ---- stage B = w1 (256x128 row-major) as fp16 m16n8k16 frag pairs ----
    // for (kc, nt, lane): k0 = kc*16 + 2*(lane&3), n = nt*8 + (lane>>2)
    //   v.x = {lo=w1[k0][n],   hi=w1[k0+1][n]}
    //   v.y = {lo=w1[k0+8][n], hi=w1[k0+9][n]}
    for (int i = tid; i < 16 * 16 * 32; i += NTHREADS) {
        int li = i & 31, nt = (i >> 5) & 15, kc = i >> 9;
        int k0 = kc * 16 + 2 * (li & 3);
        int n  = nt * 8 + (li >> 2);
        uint2 v;
        v.x = packh2(w1[k0 * 128 + n],       w1[(k0 + 1) * 128 + n]);
        v.y = packh2(w1[(k0 + 8) * 128 + n], w1[(k0 + 9) * 128 + n]);
        Bst[i] = v;
    }
    if (tid < 64) {
        b1p[tid] = ((const float2*)b1)[tid];
        w2p[tid] = ((const float2*)w2)[tid];
    }
    __syncthreads();

    const float b2v = __ldg(b2);
    const int rr   = lane >> 3;   // staging row-in-group 0..3
    const int cseg = lane & 7;    // staging float4 segment 0..7

    for (int tile = blockIdx.x; tile < NTILES; tile += NCTAS) {
        const int base = tile * 256 + warp * 32;

        // ---- per-row gather pointers into smem (row = lane) ----
        {
            int g  = base + lane;
            int gg = (g < TOTAL) ? g : (TOTAL - 1);
            const int* ei;
            const float *t0, *t1;
            int e;
            if (gg < E_CNT)          { ei = e0; t0 = zp; t1 = zo; e = gg; }
            else if (gg < 2 * E_CNT) { ei = e1; t0 = zo; t1 = zp; e = gg - E_CNT; }
            else                     { ei = e2; t0 = zo; t1 = zo; e = gg - 2 * E_CNT; }
            ulonglong2 pp;
            pp.x = (unsigned long long)(t0 + (size_t)__ldg(ei + e) * 128);
            pp.y = (unsigned long long)(t1 + (size_t)__ldg(ei + E_CNT + e) * 128);
            *(ulonglong2*)(rptr_c + lane * 16) = pp;
        }
        __syncwarp();

        // ---- accumulators: 32 edges x 128 hidden ----
        float acc[2][16][4];
#pragma unroll
        for (int mf = 0; mf < 2; mf++)
#pragma unroll
            for (int nt = 0; nt < 16; nt++)
#pragma unroll
                for (int j = 0; j < 4; j++) acc[mf][nt][j] = 0.f;

        ISSUE_STAGE(0);
        ISSUE_STAGE(1);

        // ---- 8 stages of 32 K-columns (= 2 fp16 k16-chunks) each ----
#pragma unroll 2
        for (int s = 0; s < 8; s++) {
            if (s < 6) { ISSUE_STAGE(s + 2); CP_WAIT2; }
            else if (s == 6) { CP_WAIT1; }
            else { CP_WAIT0; }
            __syncwarp();

            const char* ab = a_c + (s % 3) * STG_BYTES;
#pragma unroll
            for (int kc2 = 0; kc2 < 2; kc2++) {
                const int kcg = s * 2 + kc2;
                // A fragments: rows mf*16 + qr (+8), cols kc2*16 + 2qc (+8)
                uint32_t at[8];
#pragma unroll
                for (int mf = 0; mf < 2; mf++) {
                    const char* abase = ab + (mf * 16 + qr) * ROW_STRIDE
                                           + (kc2 * 16 + 2 * qc) * 4;
                    float2 v0 = *(const float2*)(abase);
                    float2 v1 = *(const float2*)(abase + 8 * ROW_STRIDE);
                    float2 v2 = *(const float2*)(abase + 32);
                    float2 v3 = *(const float2*)(abase + 8 * ROW_STRIDE + 32);
                    at[mf * 4 + 0] = packh2(v0.x, v0.y);
                    at[mf * 4 + 1] = packh2(v1.x, v1.y);
                    at[mf * 4 + 2] = packh2(v2.x, v2.y);
                    at[mf * 4 + 3] = packh2(v3.x, v3.y);
                }

                uint2 bA = BS(kcg, 0), bB = BS(kcg, 1), bC;
#pragma unroll
                for (int nt = 0; nt < 16; nt++) {
                    if (nt < 14) bC = BS(kcg, nt + 2);
                    MMA(acc[0][nt], at[0], at[1], at[2], at[3], bA);
                    MMA(acc[1][nt], at[4], at[5], at[6], at[7], bA);
                    bA = bB; bB = bC;
                }
            }
            __syncwarp();
        }

        // ---- epilogue: s[ri] = sum_n relu(h + b1) * w2 ----
        float s4[4] = {0.f, 0.f, 0.f, 0.f};
#pragma unroll
        for (int nt = 0; nt < 16; nt++) {
            float2 bb = b1p[nt * 4 + qc];
            float2 ww = w2p[nt * 4 + qc];
#pragma unroll
            for (int mf = 0; mf < 2; mf++) {
                float v0 = fmaxf(acc[mf][nt][0] + bb.x, 0.f);
                float v1 = fmaxf(acc[mf][nt][1] + bb.y, 0.f);
                float v2 = fmaxf(acc[mf][nt][2] + bb.x, 0.f);
                float v3 = fmaxf(acc[mf][nt][3] + bb.y, 0.f);
                s4[mf * 2]     = fmaf(v0, ww.x, fmaf(v1, ww.y, s4[mf * 2]));
                s4[mf * 2 + 1] = fmaf(v2, ww.x, fmaf(v3, ww.y, s4[mf * 2 + 1]));
            }
        }
#pragma unroll
        for (int ri = 0; ri < 4; ri++) {
            s4[ri] += __shfl_xor_sync(0xffffffffu, s4[ri], 1);
            s4[ri] += __shfl_xor_sync(0xffffffffu, s4[ri], 2);
        }
        if (qc == 0) {
#pragma unroll
            for (int ri = 0; ri < 4; ri++) {
                int g = base + qr + ri * 8;
                if (g < TOTAL) out[g] = s4[ri] + b2v;
            }
        }
    }
}

extern "C" void kernel_launch(void* const* d_in, const int* in_sizes, int n_in,
                              void* d_out, int out_size) {
    (void)in_sizes; (void)n_in; (void)out_size;
    const float* zp    = (const float*)d_in[0];
    const float* zo    = (const float*)d_in[1];
    const int*   ptnp  = (const int*)d_in[2];
    const int*   nptp  = (const int*)d_in[3];
    const int*   nptnp = (const int*)d_in[4];
    const float* w1    = (const float*)d_in[5];
    const float* b1    = (const float*)d_in[6];
    const float* w2    = (const float*)d_in[7];
    const float* b2    = (const float*)d_in[8];
    float* out = (float*)d_out;

    cudaFuncSetAttribute(edgedecoder_kernel,
                         cudaFuncAttributeMaxDynamicSharedMemorySize, SM_TOTAL);
    edgedecoder_kernel<<<NCTAS, NTHREADS, SM_TOTAL>>>(
        zp, zo, ptnp, nptp, nptnp, w1, b1, w2, b2, out);
}

// round 13
// speedup vs baseline: 2.6657x; 1.0019x over previous
#include <cuda_runtime.h>
#include <cstdint>

// EdgeDecoder: out[g] = relu(concat(zA[g], zB[g]) @ w1 + b1) @ w2 + b2
// for 3 edge types concatenated [ptnp | nptp | nptnp], E edges each.
//
// sm_103 (no 'a' features) tensor path: mma.sync m16n8k16 fp16, fp32 accum.
// Persistent, 148 CTAs x 256 threads = 4 warp PAIRS. Each pair owns 64 edges;
// within a pair each warp computes an N=64 half (M=64 x N=64 per warp).
//   - B fragment reused across 4 m-frags (halves B LDS bytes vs M=32 tiling)
//   - A staging (64 rows x 32 cols fp32, 3-deep cp.async pipeline) SHARED by
//     the pair (halves cp.async write + global bytes)
//   - ROW_STRIDE=160 -> conflict-free float2 fragment LDS
//   - epilogue: per-warp partial dot(relu(h+b1), w2), pair-reduced via smem.

#define E_CNT    500000
#define TOTAL    1500000
#define NTILES   5860            // ceil(TOTAL / 256)
#define NCTAS    148
#define NTHREADS 256

#define ROW_STRIDE 160           // 40 floats per staged row (32 + pad)
#define STG_BYTES  10240         // 64 rows * 160B

// ---- smem layout (bytes) ----
#define SM_B     0               // 65536: B frags [kc(16)][nt(16)][lane] uint2
#define SM_B1    65536           // 512: b1 as float2[64]
#define SM_W2    66048           // 512: w2 as float2[64]
#define SM_RPTR  66560           // 4096: 4 pairs x 64 rows x {p0,p1} (16B)
#define SM_RED   70656           // 2048: 4 pairs x 2 x 64 floats
#define SM_A     72704           // 122880: 4 pairs x 3 x 10240B staging
#define SM_TOTAL 195584

static __device__ __forceinline__ uint32_t s2u(const void* p) {
    uint32_t a;
    asm("{ .reg .u64 t; cvta.to.shared.u64 t, %1; cvt.u32.u64 %0, t; }"
        : "=r"(a) : "l"(p));
    return a;
}
// pack (lo, hi) fp32 -> fp16x2 register (round to nearest even)
static __device__ __forceinline__ uint32_t packh2(float lo, float hi) {
    uint32_t r;
    asm("cvt.rn.f16x2.f32 %0, %1, %2;" : "=r"(r) : "f"(hi), "f"(lo));
    return r;
}
static __device__ __forceinline__ void cp16(uint32_t dst, const void* src) {
    asm volatile("cp.async.cg.shared.global [%0], [%1], 16;"
                 :: "r"(dst), "l"(src) : "memory");
}
#define CP_COMMIT asm volatile("cp.async.commit_group;" ::: "memory")
#define CP_WAIT1  asm volatile("cp.async.wait_group 1;" ::: "memory")
#define CP_WAIT0  asm volatile("cp.async.wait_group 0;" ::: "memory")
#define PAIR_BAR  asm volatile("bar.sync %0, 64;" :: "r"(pair + 1) : "memory")

// D(16x8) += A(16x16,row,f16) * B(16x8,col,f16), fp32 accumulate in place.
#define MMA(d, A0, A1, A2, A3, B)                                        \
    asm volatile(                                                        \
        "mma.sync.aligned.m16n8k16.row.col.f32.f16.f16.f32 "             \
        "{%0,%1,%2,%3}, {%4,%5,%6,%7}, {%8,%9}, {%0,%1,%2,%3};"          \
        : "+f"((d)[0]), "+f"((d)[1]), "+f"((d)[2]), "+f"((d)[3])         \
        : "r"(A0), "r"(A1), "r"(A2), "r"(A3), "r"((B).x), "r"((B).y))

#define BS(kc, nt) Bsm[((kc) * 16 + (nt)) * 32 + lane]

// issue cp.async for one 32-col stage sn (0..7) into pair buffer sn%3.
// 64 threads of the pair each copy 8 rows x 16B.
#define ISSUE_STAGE(sn)                                                    \
    do {                                                                   \
        const int co_ = ((sn) & 3) * 32 + cseg * 4;                        \
        const uint32_t dst_ = a_s + ((sn) % 3) * STG_BYTES;                \
        _Pragma("unroll")                                                  \
        for (int r_ = 0; r_ < 8; r_++) {                                   \
            const int row_ = r_ * 8 + rtp;                                 \
            const ulonglong2 pp_ =                                         \
                *(const ulonglong2*)(rptr_c + row_ * 16);                  \
            const float* p_ = ((sn) >= 4) ? (const float*)pp_.y            \
                                          : (const float*)pp_.x;           \
            cp16(dst_ + row_ * ROW_STRIDE + cseg * 16, p_ + co_);          \
        }                                                                  \
        CP_COMMIT;                                                         \
    } while (0)

__global__ void __launch_bounds__(NTHREADS, 1)
edgedecoder_kernel(const float* __restrict__ zp, const float* __restrict__ zo,
                   const int* __restrict__ e0, const int* __restrict__ e1,
                   const int* __restrict__ e2,
                   const float* __restrict__ w1, const float* __restrict__ b1,
                   const float* __restrict__ w2, const float* __restrict__ b2,
                   float* __restrict__ out) {
    extern __shared__ char smem[];
    uint2* Bst = (uint2*)(smem + SM_B);
    const uint2* Bsm = (const uint2*)(smem + SM_B);
    float2* b1p = (float2*)(smem + SM_B1);
    float2* w2p = (float2*)(smem + SM_W2);

    const int tid  = threadIdx.x;
    const int warp = tid >> 5;
    const int lane = tid & 31;
    const int qr   = lane >> 2;   // group id 0..7
    const int qc   = lane & 3;    // thread-in-group 0..3
    const int pair = warp >> 1;   // 0..3
    const int wip  = warp & 1;    // N-half within pair
    const int tp   = tid & 63;    // thread index within pair
    const int rtp  = tp >> 3;     // staging row-in-group 0..7
    const int cseg = tp & 7;      // staging 16B segment 0..7

    const uint32_t a_s    = s2u(smem) + SM_A + pair * (3 * STG_BYTES);
    char*          a_c    = smem + SM_A + pair * (3 * STG_BYTES);
    char*          rptr_c = smem + SM_RPTR + pair * 1024;
    float*         red    = (float*)(smem + SM_RED + pair * 512);

    // ---- stage B = w1 (256x128 row-major) as fp16 m16n8k16 frag pairs ----
    for (int i = tid; i < 16 * 16 * 32; i += NTHREADS) {
        int li = i & 31, nt = (i >> 5) & 15, kc = i >> 9;
        int k0 = kc * 16 + 2 * (li & 3);
        int n  = nt * 8 + (li >> 2);
        uint2 v;
        v.x = packh2(w1[k0 * 128 + n],       w1[(k0 + 1) * 128 + n]);
        v.y = packh2(w1[(k0 + 8) * 128 + n], w1[(k0 + 9) * 128 + n]);
        Bst[i] = v;
    }
    if (tid < 64) {
        b1p[tid] = ((const float2*)b1)[tid];
        w2p[tid] = ((const float2*)w2)[tid];
    }
    __syncthreads();

    const float b2v = __ldg(b2);

    for (int tile = blockIdx.x; tile < NTILES; tile += NCTAS) {
        const int base = tile * 256 + pair * 64;

        // ---- per-row gather pointers (row = tp, 64 rows per pair) ----
        {
            int g  = base + tp;
            int gg = (g < TOTAL) ? g : (TOTAL - 1);
            const int* ei;
            const float *t0, *t1;
            int e;
            if (gg < E_CNT)          { ei = e0; t0 = zp; t1 = zo; e = gg; }
            else if (gg < 2 * E_CNT) { ei = e1; t0 = zo; t1 = zp; e = gg - E_CNT; }
            else                     { ei = e2; t0 = zo; t1 = zo; e = gg - 2 * E_CNT; }
            ulonglong2 pp;
            pp.x = (unsigned long long)(t0 + (size_t)__ldg(ei + e) * 128);
            pp.y = (unsigned long long)(t1 + (size_t)__ldg(ei + E_CNT + e) * 128);
            *(ulonglong2*)(rptr_c + tp * 16) = pp;
        }
        PAIR_BAR;

        // ---- accumulators: 64 edges x 64 hidden per warp ----
        float acc[4][8][4];
#pragma unroll
        for (int mf = 0; mf < 4; mf++)
#pragma unroll
            for (int nt = 0; nt < 8; nt++)
#pragma unroll
                for (int j = 0; j < 4; j++) acc[mf][nt][j] = 0.f;

        ISSUE_STAGE(0);
        ISSUE_STAGE(1);

        // ---- 8 stages of 32 K-columns (= 2 fp16 k16-chunks) each ----
        for (int s = 0; s < 8; s++) {
            if (s == 7) { CP_WAIT0; } else { CP_WAIT1; }
            PAIR_BAR;                       // both halves of stage s landed
            if (s < 6) ISSUE_STAGE(s + 2);  // safe: buf (s+2)%3 drained

            const char* ab = a_c + (s % 3) * STG_BYTES;
#pragma unroll
            for (int kc2 = 0; kc2 < 2; kc2++) {
                const int kcg = s * 2 + kc2;
                uint32_t at[16];
#pragma unroll
                for (int mf = 0; mf < 4; mf++) {
                    const char* abase = ab + (mf * 16 + qr) * ROW_STRIDE
                                           + (kc2 * 16 + 2 * qc) * 4;
                    float2 v0 = *(const float2*)(abase);
                    float2 v1 = *(const float2*)(abase + 8 * ROW_STRIDE);
                    float2 v2 = *(const float2*)(abase + 32);
                    float2 v3 = *(const float2*)(abase + 8 * ROW_STRIDE + 32);
                    at[mf * 4 + 0] = packh2(v0.x, v0.y);
                    at[mf * 4 + 1] = packh2(v1.x, v1.y);
                    at[mf * 4 + 2] = packh2(v2.x, v2.y);
                    at[mf * 4 + 3] = packh2(v3.x, v3.y);
                }

                uint2 bA = BS(kcg, wip * 8), bB = BS(kcg, wip * 8 + 1), bC;
#pragma unroll
                for (int nt = 0; nt < 8; nt++) {
                    if (nt < 6) bC = BS(kcg, wip * 8 + nt + 2);
                    MMA(acc[0][nt], at[0],  at[1],  at[2],  at[3],  bA);
                    MMA(acc[1][nt], at[4],  at[5],  at[6],  at[7],  bA);
                    MMA(acc[2][nt], at[8],  at[9],  at[10], at[11], bA);
                    MMA(acc[3][nt], at[12], at[13], at[14], at[15], bA);
                    bA = bB; bB = bC;
                }
            }
        }

        // ---- epilogue: partial dot over this warp's 64 n's ----
        float s4[8];
#pragma unroll
        for (int j = 0; j < 8; j++) s4[j] = 0.f;
#pragma unroll
        for (int nt = 0; nt < 8; nt++) {
            float2 bb = b1p[(wip * 8 + nt) * 4 + qc];
            float2 ww = w2p[(wip * 8 + nt) * 4 + qc];
#pragma unroll
            for (int mf = 0; mf < 4; mf++) {
                float v0 = fmaxf(acc[mf][nt][0] + bb.x, 0.f);
                float v1 = fmaxf(acc[mf][nt][1] + bb.y, 0.f);
                float v2 = fmaxf(acc[mf][nt][2] + bb.x, 0.f);
                float v3 = fmaxf(acc[mf][nt][3] + bb.y, 0.f);
                s4[mf * 2]     = fmaf(v0, ww.x, fmaf(v1, ww.y, s4[mf * 2]));
                s4[mf * 2 + 1] = fmaf(v2, ww.x, fmaf(v3, ww.y, s4[mf * 2 + 1]));
            }
        }
#pragma unroll
        for (int j = 0; j < 8; j++) {
            s4[j] += __shfl_xor_sync(0xffffffffu, s4[j], 1);
            s4[j] += __shfl_xor_sync(0xffffffffu, s4[j], 2);
        }
        if (qc == 0) {
#pragma unroll
            for (int mf = 0; mf < 4; mf++) {
                red[wip * 64 + mf * 16 + qr]     = s4[mf * 2];
                red[wip * 64 + mf * 16 + 8 + qr] = s4[mf * 2 + 1];
            }
        }
        PAIR_BAR;
        if (wip == 0) {
#pragma unroll
            for (int j = 0; j < 2; j++) {
                int e = lane + j * 32;
                int g = base + e;
                if (g < TOTAL) out[g] = red[e] + red[64 + e] + b2v;
            }
        }
    }
}

extern "C" void kernel_launch(void* const* d_in, const int* in_sizes, int n_in,
                              void* d_out, int out_size) {
    (void)in_sizes; (void)n_in; (void)out_size;
    const float* zp    = (const float*)d_in[0];
    const float* zo    = (const float*)d_in[1];
    const int*   ptnp  = (const int*)d_in[2];
    const int*   nptp  = (const int*)d_in[3];
    const int*   nptnp = (const int*)d_in[4];
    const float* w1    = (const float*)d_in[5];
    const float* b1    = (const float*)d_in[6];
    const float* w2    = (const float*)d_in[7];
    const float* b2    = (const float*)d_in[8];
    float* out = (float*)d_out;

    cudaFuncSetAttribute(edgedecoder_kernel,
                         cudaFuncAttributeMaxDynamicSharedMemorySize, SM_TOTAL);
    edgedecoder_kernel<<<NCTAS, NTHREADS, SM_TOTAL>>>(
        zp, zo, ptnp, nptp, nptnp, w1, b1, w2, b2, out);
}